// round 7
// baseline (speedup 1.0000x reference)
#include <cuda_runtime.h>
#include <cuda_fp16.h>
#include <math.h>
#include <stdint.h>

#define BB 16
#define SS 8192
#define HH 512
#define NROWS (BB*SS)

// ---------------------------------------------------------------------------
// helpers
// ---------------------------------------------------------------------------
__device__ __forceinline__ uint32_t smem_u32(const void* p) {
    uint32_t a;
    asm("{ .reg .u64 t; cvta.to.shared.u64 t, %1; cvt.u32.u64 %0, t; }" : "=r"(a) : "l"(p));
    return a;
}
#define SW128(o) ((o) ^ (((o) >> 3) & 0x70))

#define LDSM4(r0,r1,r2,r3,addr)                                               \
    asm volatile("ldmatrix.sync.aligned.m8n8.x4.shared.b16 {%0,%1,%2,%3}, [%4];" \
        : "=r"(r0),"=r"(r1),"=r"(r2),"=r"(r3) : "r"(addr))

#define CP_ASYNC16(dst, src)                                                  \
    asm volatile("cp.async.ca.shared.global [%0], [%1], 16;" :: "r"(dst), "l"(src) : "memory")
#define CP_COMMIT()  asm volatile("cp.async.commit_group;" ::: "memory")
#define CP_WAIT0()   asm volatile("cp.async.wait_group 0;" ::: "memory")

__device__ __forceinline__ void mma16816(float* c, const uint32_t* a,
                                         uint32_t b0, uint32_t b1) {
    asm volatile(
        "mma.sync.aligned.m16n8k16.row.col.f32.f16.f16.f32 "
        "{%0,%1,%2,%3}, {%4,%5,%6,%7}, {%8,%9}, {%0,%1,%2,%3};"
        : "+f"(c[0]), "+f"(c[1]), "+f"(c[2]), "+f"(c[3])
        : "r"(a[0]), "r"(a[1]), "r"(a[2]), "r"(a[3]), "r"(b0), "r"(b1));
}

__device__ __forceinline__ float fast_tanh(float x) {
    float xc = fminf(x, 30.f);
    float e  = __expf(2.f * xc);
    return __fdividef(e - 1.f, e + 1.f);
}

// ---------------------------------------------------------------------------
// scratch
// ---------------------------------------------------------------------------
__device__ float g_qproj[BB*HH];
__device__ float g_scores[BB*SS];
__device__ float g_ctx_part[BB*64*HH];
__device__ __align__(16) __half g_Wh16[HH*HH];   // W_h cast to fp16, [o][k]

// smem layout (bytes): A resident for full K (8 slots), B double-buffered
#define SM_A     0                      // 8 slots x 128 rows x 128B = 128KB
#define SM_B     131072                 // 2 stages x 128 rows x 128B = 32KB
#define SM_Q     163840                 // 128 floats
#define SM_V     164352                 // 128 floats
#define SM_PART  164864                 // 4 x 128 floats
#define SM_TOTAL 166912

// ---------------------------------------------------------------------------
// cast W_h to fp16
// ---------------------------------------------------------------------------
__global__ void whcast_kernel(const float* __restrict__ Wh) {
    int i0 = (blockIdx.x * 256 + threadIdx.x) * 4;
    float4 x = *(const float4*)(Wh + i0);
    __half2 h01 = __float22half2_rn(make_float2(x.x, x.y));
    __half2 h23 = __float22half2_rn(make_float2(x.z, x.w));
    *(uint2*)(g_Wh16 + i0) = make_uint2(*(uint32_t*)&h01, *(uint32_t*)&h23);
}

// ---------------------------------------------------------------------------
// q_proj[b][o] = query[b,:] . W_q[o,:]   (fp32, exact)
// ---------------------------------------------------------------------------
__global__ void qproj_kernel(const float* __restrict__ query,
                             const float* __restrict__ Wq) {
    int b = blockIdx.x, o = threadIdx.x;
    __shared__ float q[HH];
    q[o] = query[b*HH + o];
    __syncthreads();
    const float* w = Wq + (size_t)o*HH;
    float acc = 0.f;
#pragma unroll 8
    for (int k = 0; k < HH; k++) acc += q[k] * w[k];
    g_qproj[b*HH + o] = acc;
}

// ---------------------------------------------------------------------------
// scores, single-pass fp16 mma: D = fp16(enc) x fp16(W_h)^T (fp32 accum).
// A (128 x 512) converted ONCE into 8 resident smem slots during nc=0;
// nc=1..3 reuse resident A: inner loop is pure LDSM+MMA with B cp.async.
// ---------------------------------------------------------------------------
__global__ __launch_bounds__(256, 1)
void scores_mma_kernel(const float* __restrict__ enc,
                       const float* __restrict__ v) {
    extern __shared__ char smem[];
    const uint32_t sb = smem_u32(smem);
    const int tid  = threadIdx.x;
    const int lane = tid & 31;
    const int wid  = tid >> 5;
    const int wm   = wid & 1;          // 0..1  (64 rows each)
    const int wn   = wid >> 1;         // 0..3  (32 cols each)
    const int m0   = blockIdx.x * 128;
    const int b    = m0 / SS;

    float* qs   = (float*)(smem + SM_Q);
    float* vs   = (float*)(smem + SM_V);
    float* part = (float*)(smem + SM_PART);   // [4][128]

    // per-thread ldmatrix base offsets (within a 128-row x 128B tile)
    const uint32_t aRow = (uint32_t)(wm*64 + (lane & 15)) * 128u;
    const uint32_t aCol = ((lane >> 4) & 1) * 16u;
    const uint32_t bRow = (uint32_t)(wn*32 + (lane & 7) + ((lane & 16) ? 8 : 0)) * 128u;
    const uint32_t bCol = ((lane & 8) ? 16u : 0u);

    const uint4* wsrc = (const uint4*)g_Wh16;   // 64 uint4 per o-row

    float rowsc[8];
#pragma unroll
    for (int i = 0; i < 8; i++) rowsc[i] = 0.f;

    for (int nc = 0; nc < 4; nc++) {
        if (tid < 128) {
            qs[tid] = g_qproj[b*HH + nc*128 + tid];
            vs[tid] = v[nc*128 + tid];
        }

        float c[4][4][4];
#pragma unroll
        for (int mf = 0; mf < 4; mf++)
#pragma unroll
            for (int nf = 0; nf < 4; nf++)
#pragma unroll
                for (int e = 0; e < 4; e++) c[mf][nf][e] = 0.f;

        // ---- prologue for this nc: stage-0 B (and, nc==0 only, A slot 0)
        if (nc == 0) {
#pragma unroll
            for (int i = 0; i < 8; i++) {               // A kc=0: 128x64 fp32->fp16
                int f = tid + i*256;
                int m = f >> 4, jq = f & 15;
                float4 x = *(const float4*)(enc + (size_t)(m0+m)*HH + jq*4);
                __half2 h01 = __float22half2_rn(make_float2(x.x, x.y));
                __half2 h23 = __float22half2_rn(make_float2(x.z, x.w));
                uint32_t off = SW128((uint32_t)(m*128 + jq*8));
                *(uint2*)(smem + SM_A + off) =
                    make_uint2(*(uint32_t*)&h01, *(uint32_t*)&h23);
            }
        }
#pragma unroll
        for (int i = 0; i < 4; i++) {                   // B kc=0: 128 rows x 128B
            int f = tid + i*256;
            int n = f >> 3, j = f & 7;
            uint32_t dst = sb + SM_B + SW128((uint32_t)(n*128 + j*16));
            CP_ASYNC16(dst, wsrc + (nc*128 + n)*64 + j);
        }
        CP_COMMIT();
        CP_WAIT0();
        __syncthreads();

        for (int kc = 0; kc < 8; kc++) {
            // ---- issue loads for kc+1 (overlap with MMA below)
            if (kc < 7) {
                const int kn = kc + 1;
                if (nc == 0) {                          // A slot kn (once ever)
#pragma unroll
                    for (int i = 0; i < 8; i++) {
                        int f = tid + i*256;
                        int m = f >> 4, jq = f & 15;
                        float4 x = *(const float4*)(enc + (size_t)(m0+m)*HH + kn*64 + jq*4);
                        __half2 h01 = __float22half2_rn(make_float2(x.x, x.y));
                        __half2 h23 = __float22half2_rn(make_float2(x.z, x.w));
                        uint32_t off = SW128((uint32_t)(m*128 + jq*8));
                        *(uint2*)(smem + SM_A + kn*16384 + off) =
                            make_uint2(*(uint32_t*)&h01, *(uint32_t*)&h23);
                    }
                }
#pragma unroll
                for (int i = 0; i < 4; i++) {           // B stage kn&1
                    int f = tid + i*256;
                    int n = f >> 3, j = f & 7;
                    uint32_t dst = sb + SM_B + (uint32_t)(kn & 1)*16384u +
                                   SW128((uint32_t)(n*128 + j*16));
                    CP_ASYNC16(dst, wsrc + (nc*128 + n)*64 + kn*8 + j);
                }
                CP_COMMIT();
            }

            // ---- MMAs: A from resident slot kc, B from stage kc&1
            const uint32_t aBase = sb + SM_A + (uint32_t)kc*16384u;
            const uint32_t bBase = sb + SM_B + (uint32_t)(kc & 1)*16384u;
#pragma unroll
            for (int ks = 0; ks < 4; ks++) {
                uint32_t a[4][4];
#pragma unroll
                for (int mf = 0; mf < 4; mf++) {
                    uint32_t ad = aBase +
                        SW128(aRow + (uint32_t)mf*2048u + (uint32_t)ks*32u + aCol);
                    LDSM4(a[mf][0], a[mf][1], a[mf][2], a[mf][3], ad);
                }
                uint32_t bfr[4][2];
#pragma unroll
                for (int n2 = 0; n2 < 2; n2++) {
                    uint32_t bd = bBase +
                        SW128(bRow + (uint32_t)n2*2048u + (uint32_t)ks*32u + bCol);
                    uint32_t r0, r1, r2, r3;
                    LDSM4(r0, r1, r2, r3, bd);
                    bfr[n2*2][0] = r0;   bfr[n2*2][1] = r1;
                    bfr[n2*2+1][0] = r2; bfr[n2*2+1][1] = r3;
                }
#pragma unroll
                for (int mf = 0; mf < 4; mf++)
#pragma unroll
                    for (int nf = 0; nf < 4; nf++)
                        mma16816(c[mf][nf], a[mf], bfr[nf][0], bfr[nf][1]);
            }

            CP_WAIT0();        // next-stage loads landed (overlapped with MMAs)
            __syncthreads();   // B stage reuse + (nc==0) A slot visibility
        }

        // ---- epilogue for this 128-channel chunk
#pragma unroll
        for (int mf = 0; mf < 4; mf++)
#pragma unroll
            for (int nf = 0; nf < 4; nf++) {
                int nb = wn*32 + nf*8 + (lane & 3)*2;
                float q0 = qs[nb],   v0 = vs[nb];
                float q1 = qs[nb+1], v1 = vs[nb+1];
                rowsc[mf*2]   += fast_tanh(c[mf][nf][0] + q0)*v0
                               + fast_tanh(c[mf][nf][1] + q1)*v1;
                rowsc[mf*2+1] += fast_tanh(c[mf][nf][2] + q0)*v0
                               + fast_tanh(c[mf][nf][3] + q1)*v1;
            }
        __syncthreads();   // before qs/vs overwritten next nc
    }

    // reduce over the 4 lanes sharing each row
#pragma unroll
    for (int i = 0; i < 8; i++) {
        rowsc[i] += __shfl_xor_sync(~0u, rowsc[i], 1);
        rowsc[i] += __shfl_xor_sync(~0u, rowsc[i], 2);
    }
    if ((lane & 3) == 0) {
        int r = lane >> 2;
#pragma unroll
        for (int mf = 0; mf < 4; mf++) {
            part[wn*128 + wm*64 + mf*16 + r]     = rowsc[mf*2];
            part[wn*128 + wm*64 + mf*16 + r + 8] = rowsc[mf*2+1];
        }
    }
    __syncthreads();
    if (tid < 128)
        g_scores[m0 + tid] = part[tid] + part[128+tid] + part[256+tid] + part[384+tid];
}

// ---------------------------------------------------------------------------
// softmax over S per batch
// ---------------------------------------------------------------------------
__global__ void softmax_kernel(float* __restrict__ alpha) {
    const int b = blockIdx.x;
    const int tid = threadIdx.x;    // 1024
    const float* sc = g_scores + b*SS;
    __shared__ float red[32];

    float m = -1e30f;
    for (int s = tid; s < SS; s += 1024) m = fmaxf(m, sc[s]);
#pragma unroll
    for (int off = 16; off; off >>= 1) m = fmaxf(m, __shfl_xor_sync(~0u, m, off));
    if ((tid & 31) == 0) red[tid >> 5] = m;
    __syncthreads();
    if (tid < 32) {
        float x = red[tid];
#pragma unroll
        for (int off = 16; off; off >>= 1) x = fmaxf(x, __shfl_xor_sync(~0u, x, off));
        if (tid == 0) red[0] = x;
    }
    __syncthreads();
    m = red[0];
    __syncthreads();

    float sum = 0.f;
    for (int s = tid; s < SS; s += 1024) sum += expf(sc[s] - m);
#pragma unroll
    for (int off = 16; off; off >>= 1) sum += __shfl_xor_sync(~0u, sum, off);
    if ((tid & 31) == 0) red[tid >> 5] = sum;
    __syncthreads();
    if (tid < 32) {
        float x = red[tid];
#pragma unroll
        for (int off = 16; off; off >>= 1) x += __shfl_xor_sync(~0u, x, off);
        if (tid == 0) red[0] = x;
    }
    __syncthreads();
    const float inv = 1.f / red[0];
    for (int s = tid; s < SS; s += 1024)
        alpha[b*SS + s] = expf(sc[s] - m) * inv;
}

// ---------------------------------------------------------------------------
// context: partials over 64 s-chunks of 128 rows, then reduce
// ---------------------------------------------------------------------------
__global__ void ctx_part_kernel(const float* __restrict__ enc,
                                const float* __restrict__ alpha) {
    const int b = blockIdx.x, sc = blockIdx.y;   // 16 x 64
    const int t = threadIdx.x;                    // 128
    __shared__ float al[128];
    al[t] = alpha[b*SS + sc*128 + t];
    __syncthreads();

    const float4* e = (const float4*)(enc + (size_t)b*SS*HH + (size_t)sc*128*HH) + t;
    float4 acc = make_float4(0.f, 0.f, 0.f, 0.f);
#pragma unroll 8
    for (int s = 0; s < 128; s++) {
        float a = al[s];
        float4 vv = e[(size_t)s*128];
        acc.x += a*vv.x; acc.y += a*vv.y; acc.z += a*vv.z; acc.w += a*vv.w;
    }
    ((float4*)(g_ctx_part + (size_t)(b*64 + sc)*HH))[t] = acc;
}

__global__ void ctx_reduce_kernel(float* __restrict__ ctx) {
    const int b = blockIdx.x, h = threadIdx.x;
    float s = 0.f;
#pragma unroll
    for (int i = 0; i < 64; i++)
        s += g_ctx_part[(size_t)(b*64 + i)*HH + h];
    ctx[b*HH + h] = s;
}

// ---------------------------------------------------------------------------
extern "C" void kernel_launch(void* const* d_in, const int* in_sizes, int n_in,
                              void* d_out, int out_size) {
    const float* enc   = (const float*)d_in[0];
    const float* query = (const float*)d_in[1];
    const float* Wh    = (const float*)d_in[2];
    const float* Wq    = (const float*)d_in[3];
    const float* v     = (const float*)d_in[4];

    float* ctx   = (float*)d_out;
    float* alpha = (float*)d_out + BB*HH;

    cudaFuncSetAttribute(scores_mma_kernel,
                         cudaFuncAttributeMaxDynamicSharedMemorySize, SM_TOTAL);

    whcast_kernel<<<HH*HH/1024, 256>>>(Wh);
    qproj_kernel<<<BB, HH>>>(query, Wq);
    scores_mma_kernel<<<NROWS/128, 256, SM_TOTAL>>>(enc, v);
    softmax_kernel<<<BB, 1024>>>(alpha);
    ctx_part_kernel<<<dim3(BB, 64), 128>>>(enc, alpha);
    ctx_reduce_kernel<<<BB, HH>>>(ctx);
}